// round 1
// baseline (speedup 1.0000x reference)
#include <cuda_runtime.h>
#include <cuda_bf16.h>

#define Tt 3
#define Ll 4
#define Mm 3
#define Bb 8
#define Cc 64
#define Hh 128
#define Ww 128
#define HWp (Hh*Ww)
#define TILE 16
#define CCHUNK 8

// routing selections [T][L]
__device__ int g_sel[Tt*Ll];
// ping-pong activations: [2][T*B*C*H*W] = 2 * 100.7MB
__device__ float g_act[2][(size_t)Tt*Bb*Cc*HWp];

// ---------------- packed f32x2 helpers ----------------
__device__ __forceinline__ unsigned long long pk2(float lo, float hi) {
    unsigned long long r;
    asm("mov.b64 %0, {%1, %2};" : "=l"(r) : "f"(lo), "f"(hi));
    return r;
}
__device__ __forceinline__ void upk2(unsigned long long v, float& lo, float& hi) {
    asm("mov.b64 {%0, %1}, %2;" : "=f"(lo), "=f"(hi) : "l"(v));
}
__device__ __forceinline__ unsigned long long fma2(unsigned long long a,
                                                   unsigned long long b,
                                                   unsigned long long c) {
    unsigned long long d;
    asm("fma.rn.f32x2 %0, %1, %2, %3;" : "=l"(d) : "l"(a), "l"(b), "l"(c));
    return d;
}

// ---------------- routing: argmax(a + g) per (task, layer) ----------------
__global__ void routing_kernel(const float* __restrict__ alpha0,
                               const float* __restrict__ alphas,
                               const float* __restrict__ g0,
                               const float* __restrict__ gs) {
    int t = threadIdx.x;
    if (t >= Tt) return;
    // layer 0: alpha0 [T,1,M], g0 [T,1,M]
    int idx = 0;
    {
        float best = -1e30f; int bi = 0;
        #pragma unroll
        for (int m = 0; m < Mm; m++) {
            float v = alpha0[t*Mm + m] + g0[t*Mm + m];
            if (v > best) { best = v; bi = m; }
        }
        idx = bi;
        g_sel[t*Ll + 0] = bi;
    }
    // layers 1..L-1: alphas [L-1,T,M,M], gather row idx
    for (int l = 1; l < Ll; l++) {
        const float* a = alphas + ((((size_t)(l-1)*Tt + t)*Mm + idx)*Mm);
        const float* g = gs     + ((((size_t)(l-1)*Tt + t)*Mm + idx)*Mm);
        float best = -1e30f; int bi = 0;
        #pragma unroll
        for (int m = 0; m < Mm; m++) {
            float v = a[m] + g[m];
            if (v > best) { best = v; bi = m; }
        }
        idx = bi;
        g_sel[t*Ll + l] = bi;
    }
}

// ---------------- 3x3 SAME conv + bias + relu, module selected by g_sel ----
// grid: (W/16, H/16, T*B), block: 256 (16x16)
__global__ void __launch_bounds__(256) conv_kernel(
    const float* __restrict__ x,
    const float* __restrict__ enc_w,
    const float* __restrict__ enc_b,
    int layer, int ibuf, int obuf)
{
    __shared__ __align__(16) float s_in[CCHUNK][18][18];
    __shared__ __align__(16) float s_w[CCHUNK][9][Cc];

    const int tid = threadIdx.x;
    const int tx = tid & 15, ty = tid >> 4;
    const int z = blockIdx.z;
    const int b = z % Bb;
    const int t = z / Bb;
    const int tileX = blockIdx.x * TILE, tileY = blockIdx.y * TILE;

    const int m = g_sel[t*Ll + layer];
    const float* wbase = enc_w + (size_t)(layer*Mm + m) * Cc * Cc * 9;
    const float* bbase = enc_b + (size_t)(layer*Mm + m) * Cc;
    const float* in = (ibuf < 0) ? (x + (size_t)b * Cc * HWp)
                                 : (g_act[ibuf] + (size_t)(t*Bb + b) * Cc * HWp);
    float* out = g_act[obuf] + (size_t)(t*Bb + b) * Cc * HWp;

    unsigned long long acc[32];
    #pragma unroll
    for (int i = 0; i < 32; i++) acc[i] = 0ULL;  // (0.f, 0.f)

    const int gy = tileY + ty, gx = tileX + tx;

    for (int cc = 0; cc < Cc; cc += CCHUNK) {
        __syncthreads();
        // stage input tile with halo (zero-pad OOB)
        for (int i = tid; i < CCHUNK*18*18; i += 256) {
            int c = i / 324;
            int rem = i - c*324;
            int r = rem / 18, col = rem - r*18;
            int iy = tileY + r - 1, ix = tileX + col - 1;
            float v = 0.f;
            if (iy >= 0 && iy < Hh && ix >= 0 && ix < Ww)
                v = in[(size_t)(cc + c)*HWp + iy*Ww + ix];
            s_in[c][r][col] = v;
        }
        // stage weights: s_w[c][tap][oc]  (global OIHW: wbase[(oc*Cc+ic)*9 + tap])
        for (int i = tid; i < CCHUNK*9*Cc; i += 256) {
            int c = i / (9*Cc);
            int rem = i - c*(9*Cc);
            int tap = rem >> 6;
            int oc  = rem & 63;
            s_w[c][tap][oc] = wbase[((size_t)oc*Cc + cc + c)*9 + tap];
        }
        __syncthreads();

        #pragma unroll
        for (int c = 0; c < CCHUNK; c++) {
            unsigned long long iv[9];
            #pragma unroll
            for (int ky = 0; ky < 3; ky++)
                #pragma unroll
                for (int kx = 0; kx < 3; kx++) {
                    float v = s_in[c][ty + ky][tx + kx];
                    iv[ky*3 + kx] = pk2(v, v);
                }
            #pragma unroll
            for (int tap = 0; tap < 9; tap++) {
                const unsigned long long* wrow =
                    reinterpret_cast<const unsigned long long*>(&s_w[c][tap][0]);
                #pragma unroll
                for (int q = 0; q < 8; q++) {
                    // LDS.128: two packed (oc,oc+1) weight pairs
                    ulonglong2 wv = reinterpret_cast<const ulonglong2*>(wrow)[q];
                    acc[4*q + 0] = fma2(iv[tap], wv.x, acc[4*q + 0]);
                    acc[4*q + 1] = fma2(iv[tap], wv.y, acc[4*q + 1]);
                }
                #pragma unroll
                for (int q = 0; q < 8; q++) {
                    ulonglong2 wv = reinterpret_cast<const ulonglong2*>(wrow)[8 + q];
                    acc[4*q + 2] = fma2(iv[tap], wv.x, acc[4*q + 2]);
                    acc[4*q + 3] = fma2(iv[tap], wv.y, acc[4*q + 3]);
                }
            }
        }
    }

    // epilogue: bias + relu + store
    #pragma unroll
    for (int q = 0; q < 8; q++) {
        #pragma unroll
        for (int j = 0; j < 4; j++) {
            int p = 4*q + j;
            int oc;
            // mapping: acc[4q+0]->oc 4q*2? reconstruct: pairs q covers ocs [8q..8q+3] from
            // first wrow block and [8q+... ] -- recompute directly:
            // first loop:  acc[4q+0] = ocs (8q+0,8q+1), acc[4q+1] = (8q+2,8q+3)
            // second loop: acc[4q+2] = ocs (64+16q... no:
            // wrow[8+q] pair index = 8+q -> ocs (2*(2*(8+q))...) careful below.
            (void)p; (void)j; (void)oc;
        }
    }
    // Explicit, unambiguous epilogue:
    // wrow element k (ulonglong) = ocs (2k, 2k+1). ulonglong2 index q -> elements 2q, 2q+1.
    // First loop  (q=0..7):  acc[4q+0] <- ocs(4q,4q+1),   acc[4q+1] <- ocs(4q+2,4q+3)
    // Second loop (q=0..7):  acc[4q+2] <- ocs(32+4q,33+4q), acc[4q+3] <- ocs(34+4q,35+4q)
    #pragma unroll
    for (int q = 0; q < 8; q++) {
        int ocs[4] = {4*q, 4*q + 2, 32 + 4*q, 34 + 4*q};
        #pragma unroll
        for (int j = 0; j < 4; j++) {
            float lo, hi;
            upk2(acc[4*q + j], lo, hi);
            int oc = ocs[j];
            lo = fmaxf(lo + bbase[oc], 0.f);
            hi = fmaxf(hi + bbase[oc + 1], 0.f);
            out[(size_t)oc*HWp + gy*Ww + gx] = lo;
            out[(size_t)(oc + 1)*HWp + gy*Ww + gx] = hi;
        }
    }
}

// ---------------- decoder: 1x1 conv -> 3 ch, normalize for task 2 ----------
__global__ void __launch_bounds__(256) decoder_kernel(
    const float* __restrict__ dec_w, const float* __restrict__ dec_b,
    float* __restrict__ out, int ibuf)
{
    int idx = blockIdx.x * 256 + threadIdx.x;      // Tt*Bb*HWp = 393216
    int px = idx & (HWp - 1);
    int tb = idx >> 14;                            // HWp = 16384 = 2^14
    int b = tb % Bb;
    int t = tb / Bb;

    const float* hp = g_act[ibuf] + (size_t)(t*Bb + b) * Cc * HWp + px;
    const float* w = dec_w + (size_t)t * 3 * Cc;   // [T,3,C,1,1]
    float a0 = dec_b[t*3 + 0];
    float a1 = dec_b[t*3 + 1];
    float a2 = dec_b[t*3 + 2];
    #pragma unroll 8
    for (int c = 0; c < Cc; c++) {
        float v = hp[(size_t)c * HWp];
        a0 = fmaf(v, w[c], a0);
        a1 = fmaf(v, w[Cc + c], a1);
        a2 = fmaf(v, w[2*Cc + c], a2);
    }
    if (t == 2) {  // 'normal' task: y / ||y||_channel
        float n = rsqrtf(a0*a0 + a1*a1 + a2*a2);
        a0 *= n; a1 *= n; a2 *= n;
    }
    float* op = out + ((size_t)(t*Bb + b) * 3) * HWp + px;
    op[0] = a0;
    op[HWp] = a1;
    op[2*HWp] = a2;
}

extern "C" void kernel_launch(void* const* d_in, const int* in_sizes, int n_in,
                              void* d_out, int out_size) {
    const float* x      = (const float*)d_in[0];
    const float* alpha0 = (const float*)d_in[1];
    const float* alphas = (const float*)d_in[2];
    const float* g0     = (const float*)d_in[3];
    const float* gs     = (const float*)d_in[4];
    const float* enc_w  = (const float*)d_in[5];
    const float* enc_b  = (const float*)d_in[6];
    const float* dec_w  = (const float*)d_in[7];
    const float* dec_b  = (const float*)d_in[8];
    float* out = (float*)d_out;

    routing_kernel<<<1, 32>>>(alpha0, alphas, g0, gs);

    dim3 grid(Ww / TILE, Hh / TILE, Tt * Bb);
    // layer 0: x -> buf0 ; 1: buf0 -> buf1 ; 2: buf1 -> buf0 ; 3: buf0 -> buf1
    conv_kernel<<<grid, 256>>>(x, enc_w, enc_b, 0, -1, 0);
    conv_kernel<<<grid, 256>>>(x, enc_w, enc_b, 1,  0, 1);
    conv_kernel<<<grid, 256>>>(x, enc_w, enc_b, 2,  1, 0);
    conv_kernel<<<grid, 256>>>(x, enc_w, enc_b, 3,  0, 1);

    decoder_kernel<<<(Tt*Bb*HWp) / 256, 256>>>(dec_w, dec_b, out, 1);
}

// round 2
// speedup vs baseline: 3.4901x; 3.4901x over previous
#include <cuda_runtime.h>
#include <cuda_bf16.h>
#include <cstdint>

#define Tt 3
#define Ll 4
#define Mm 3
#define Bb 8
#define Cc 64
#define Hh 128
#define Ww 128
#define HWp (Hh*Ww)
#define TILE 16
#define CCHUNK 4
#define NCHUNK (Cc/CCHUNK)

// routing selections [T][L]
__device__ int g_sel[Tt*Ll];
// transposed weights: [L*M][ic][tap][oc]
__device__ __align__(128) float g_wT[(size_t)Ll*Mm*Cc*9*Cc];
// ping-pong activations: [2][T*B*C*H*W]
__device__ __align__(128) float g_act[2][(size_t)Tt*Bb*Cc*HWp];

// ---------------- packed f32x2 helpers ----------------
__device__ __forceinline__ unsigned long long pk2(float lo, float hi) {
    unsigned long long r;
    asm("mov.b64 %0, {%1, %2};" : "=l"(r) : "f"(lo), "f"(hi));
    return r;
}
__device__ __forceinline__ void upk2(unsigned long long v, float& lo, float& hi) {
    asm("mov.b64 {%0, %1}, %2;" : "=f"(lo), "=f"(hi) : "l"(v));
}
__device__ __forceinline__ unsigned long long fma2(unsigned long long a,
                                                   unsigned long long b,
                                                   unsigned long long c) {
    unsigned long long d;
    asm("fma.rn.f32x2 %0, %1, %2, %3;" : "=l"(d) : "l"(a), "l"(b), "l"(c));
    return d;
}

// ---------------- cp.async helpers ----------------
__device__ __forceinline__ void cp_async4(void* smem_dst, const void* gmem_src, bool pred) {
    uint32_t saddr = (uint32_t)__cvta_generic_to_shared(smem_dst);
    int sz = pred ? 4 : 0;
    asm volatile("cp.async.ca.shared.global [%0], [%1], 4, %2;"
                 :: "r"(saddr), "l"(gmem_src), "r"(sz) : "memory");
}
__device__ __forceinline__ void cp_async16(void* smem_dst, const void* gmem_src) {
    uint32_t saddr = (uint32_t)__cvta_generic_to_shared(smem_dst);
    asm volatile("cp.async.cg.shared.global [%0], [%1], 16;"
                 :: "r"(saddr), "l"(gmem_src) : "memory");
}
__device__ __forceinline__ void cp_commit() {
    asm volatile("cp.async.commit_group;" ::: "memory");
}
template <int N>
__device__ __forceinline__ void cp_wait() {
    asm volatile("cp.async.wait_group %0;" :: "n"(N) : "memory");
}

// ---------------- routing: argmax(a + g) per (task, layer) ----------------
__global__ void routing_kernel(const float* __restrict__ alpha0,
                               const float* __restrict__ alphas,
                               const float* __restrict__ g0,
                               const float* __restrict__ gs) {
    int t = threadIdx.x;
    if (t >= Tt) return;
    int idx = 0;
    {
        float best = -1e30f; int bi = 0;
        #pragma unroll
        for (int m = 0; m < Mm; m++) {
            float v = alpha0[t*Mm + m] + g0[t*Mm + m];
            if (v > best) { best = v; bi = m; }
        }
        idx = bi;
        g_sel[t*Ll + 0] = bi;
    }
    for (int l = 1; l < Ll; l++) {
        const float* a = alphas + ((((size_t)(l-1)*Tt + t)*Mm + idx)*Mm);
        const float* g = gs     + ((((size_t)(l-1)*Tt + t)*Mm + idx)*Mm);
        float best = -1e30f; int bi = 0;
        #pragma unroll
        for (int m = 0; m < Mm; m++) {
            float v = a[m] + g[m];
            if (v > best) { best = v; bi = m; }
        }
        idx = bi;
        g_sel[t*Ll + l] = bi;
    }
}

// ---------------- weight transpose: OIHW -> [mod][ic][tap][oc] -------------
__global__ void __launch_bounds__(256) transpose_w_kernel(const float* __restrict__ enc_w) {
    int i = blockIdx.x * 256 + threadIdx.x;       // total L*M*64*9*64 = 442368
    int oc  = i & 63;
    int tap = (i >> 6) % 9;
    int ic  = (i / 576) & 63;
    int mod = i / 36864;
    g_wT[i] = enc_w[(((size_t)(mod*Cc + oc))*Cc + ic)*9 + tap];
}

// ---------------- 3x3 SAME conv + bias + relu ------------------------------
// block computes 16x16 px tile x 64 oc. 256 threads:
//   tid = ocg*64 + p ; ocg in 0..3 (16 ocs), p: py=p>>2 (0..15), px0=(p&3)*4
// each thread: 4 consecutive pixels (px0..px0+3, row py) x 16 output channels.
__global__ void __launch_bounds__(256) conv_kernel(
    const float* __restrict__ x,
    const float* __restrict__ enc_b,
    int layer, int ibuf, int obuf)
{
    __shared__ __align__(16) float s_in[2][CCHUNK][18][19];
    __shared__ __align__(16) float s_w[2][CCHUNK][9][Cc];

    const int tid = threadIdx.x;
    const int ocg = tid >> 6;
    const int p   = tid & 63;
    const int py  = p >> 2;
    const int px0 = (p & 3) * 4;
    const int z = blockIdx.z;
    const int b = z % Bb;
    const int t = z / Bb;
    const int tileX = blockIdx.x * TILE, tileY = blockIdx.y * TILE;

    const int m = g_sel[t*Ll + layer];
    const float* wT = g_wT + (size_t)(layer*Mm + m) * Cc * 9 * Cc;
    const float* bbase = enc_b + (size_t)(layer*Mm + m) * Cc;
    const float* in = (ibuf < 0) ? (x + (size_t)b * Cc * HWp)
                                 : (g_act[ibuf] + (size_t)(t*Bb + b) * Cc * HWp);
    float* out = g_act[obuf] + (size_t)(t*Bb + b) * Cc * HWp;

    unsigned long long acc[4][8];
    #pragma unroll
    for (int pp = 0; pp < 4; pp++)
        #pragma unroll
        for (int q = 0; q < 8; q++) acc[pp][q] = 0ULL;

    // ---- staging lambda (chunk cc_i -> buffer buf) ----
    auto stage = [&](int cc_i, int buf) {
        const int cc = cc_i * CCHUNK;
        // input tile with halo: 4 x 18 x 18 elements
        #pragma unroll
        for (int i = tid; i < CCHUNK*18*18; i += 256) {
            int c = i / 324;
            int rem = i - c*324;
            int r = rem / 18, col = rem - r*18;
            int iy = tileY + r - 1, ix = tileX + col - 1;
            bool inb = (iy >= 0) & (iy < Hh) & (ix >= 0) & (ix < Ww);
            int iyc = inb ? iy : 0, ixc = inb ? ix : 0;
            cp_async4(&s_in[buf][c][r][col],
                      in + (size_t)(cc + c)*HWp + iyc*Ww + ixc, inb);
        }
        // weights: contiguous 4*9*64 = 2304 floats = 576 float4
        const float* src = wT + (size_t)cc * 9 * Cc;
        float* dst = &s_w[buf][0][0][0];
        #pragma unroll
        for (int i = tid; i < 576; i += 256) {
            cp_async16(dst + i*4, src + i*4);
        }
        cp_commit();
    };

    stage(0, 0);

    for (int k = 0; k < NCHUNK; k++) {
        const int buf = k & 1;
        __syncthreads();                 // buf (k+1)&1 free (compute k-1 done)
        if (k + 1 < NCHUNK) stage(k + 1, (k + 1) & 1);
        if (k + 1 < NCHUNK) cp_wait<1>(); else cp_wait<0>();
        __syncthreads();                 // chunk k visible to all

        #pragma unroll
        for (int c = 0; c < CCHUNK; c++) {
            // cache 3x6 input patch as packed pairs
            unsigned long long iv[3][6];
            #pragma unroll
            for (int r = 0; r < 3; r++)
                #pragma unroll
                for (int j = 0; j < 6; j++) {
                    float v = s_in[buf][c][py + r][px0 + j];
                    iv[r][j] = pk2(v, v);
                }
            const ulonglong2* wp =
                reinterpret_cast<const ulonglong2*>(&s_w[buf][c][0][ocg*16]);
            #pragma unroll
            for (int ky = 0; ky < 3; ky++)
                #pragma unroll
                for (int kx = 0; kx < 3; kx++) {
                    const int tap = ky*3 + kx;
                    ulonglong2 w0 = wp[tap*16 + 0];
                    ulonglong2 w1 = wp[tap*16 + 1];
                    ulonglong2 w2 = wp[tap*16 + 2];
                    ulonglong2 w3 = wp[tap*16 + 3];
                    #pragma unroll
                    for (int pp = 0; pp < 4; pp++) {
                        unsigned long long v = iv[ky][kx + pp];
                        acc[pp][0] = fma2(v, w0.x, acc[pp][0]);
                        acc[pp][1] = fma2(v, w0.y, acc[pp][1]);
                        acc[pp][2] = fma2(v, w1.x, acc[pp][2]);
                        acc[pp][3] = fma2(v, w1.y, acc[pp][3]);
                        acc[pp][4] = fma2(v, w2.x, acc[pp][4]);
                        acc[pp][5] = fma2(v, w2.y, acc[pp][5]);
                        acc[pp][6] = fma2(v, w3.x, acc[pp][6]);
                        acc[pp][7] = fma2(v, w3.y, acc[pp][7]);
                    }
                }
        }
    }

    // epilogue: bias + relu + float4 stores
    const int gy = tileY + py;
    const int gx0 = tileX + px0;
    #pragma unroll
    for (int q = 0; q < 8; q++) {
        const int oc = ocg*16 + q*2;
        const float b0 = bbase[oc], b1 = bbase[oc + 1];
        float lo[4], hi[4];
        #pragma unroll
        for (int pp = 0; pp < 4; pp++) {
            float l, h;
            upk2(acc[pp][q], l, h);
            lo[pp] = fmaxf(l + b0, 0.f);
            hi[pp] = fmaxf(h + b1, 0.f);
        }
        *reinterpret_cast<float4*>(out + (size_t)oc*HWp + gy*Ww + gx0) =
            make_float4(lo[0], lo[1], lo[2], lo[3]);
        *reinterpret_cast<float4*>(out + (size_t)(oc+1)*HWp + gy*Ww + gx0) =
            make_float4(hi[0], hi[1], hi[2], hi[3]);
    }
}

// ---------------- decoder: 1x1 conv -> 3 ch, normalize for task 2 ----------
__global__ void __launch_bounds__(256) decoder_kernel(
    const float* __restrict__ dec_w, const float* __restrict__ dec_b,
    float* __restrict__ out, int ibuf)
{
    int idx = blockIdx.x * 256 + threadIdx.x;      // Tt*Bb*HWp
    int px = idx & (HWp - 1);
    int tb = idx >> 14;
    int b = tb % Bb;
    int t = tb / Bb;

    const float* hp = g_act[ibuf] + (size_t)(t*Bb + b) * Cc * HWp + px;
    const float* w = dec_w + (size_t)t * 3 * Cc;
    float a0 = dec_b[t*3 + 0];
    float a1 = dec_b[t*3 + 1];
    float a2 = dec_b[t*3 + 2];
    #pragma unroll 8
    for (int c = 0; c < Cc; c++) {
        float v = hp[(size_t)c * HWp];
        a0 = fmaf(v, w[c], a0);
        a1 = fmaf(v, w[Cc + c], a1);
        a2 = fmaf(v, w[2*Cc + c], a2);
    }
    if (t == 2) {
        float n = rsqrtf(a0*a0 + a1*a1 + a2*a2);
        a0 *= n; a1 *= n; a2 *= n;
    }
    float* op = out + ((size_t)(t*Bb + b) * 3) * HWp + px;
    op[0] = a0;
    op[HWp] = a1;
    op[2*HWp] = a2;
}

extern "C" void kernel_launch(void* const* d_in, const int* in_sizes, int n_in,
                              void* d_out, int out_size) {
    const float* x      = (const float*)d_in[0];
    const float* alpha0 = (const float*)d_in[1];
    const float* alphas = (const float*)d_in[2];
    const float* g0     = (const float*)d_in[3];
    const float* gs     = (const float*)d_in[4];
    const float* enc_w  = (const float*)d_in[5];
    const float* enc_b  = (const float*)d_in[6];
    const float* dec_w  = (const float*)d_in[7];
    const float* dec_b  = (const float*)d_in[8];
    float* out = (float*)d_out;

    routing_kernel<<<1, 32>>>(alpha0, alphas, g0, gs);
    transpose_w_kernel<<<(Ll*Mm*Cc*9*Cc)/256, 256>>>(enc_w);

    dim3 grid(Ww / TILE, Hh / TILE, Tt * Bb);
    conv_kernel<<<grid, 256>>>(x, enc_b, 0, -1, 0);
    conv_kernel<<<grid, 256>>>(x, enc_b, 1,  0, 1);
    conv_kernel<<<grid, 256>>>(x, enc_b, 2,  1, 0);
    conv_kernel<<<grid, 256>>>(x, enc_b, 3,  0, 1);

    decoder_kernel<<<(Tt*Bb*HWp) / 256, 256>>>(dec_w, dec_b, out, 1);
}

// round 4
// speedup vs baseline: 8.0862x; 2.3169x over previous
#include <cuda_runtime.h>
#include <cuda_bf16.h>
#include <cstdint>

#define Tt 3
#define Ll 4
#define Mm 3
#define Bb 8
#define Cc 64
#define Hh 128
#define Ww 128
#define HWp (Hh*Ww)
#define PW 130
#define PPX (PW*PW)              // 16900 padded pixels
#define FRONT 256
#define SLACK 384
#define PTOT (FRONT + PPX + SLACK)

#define TILE_M 256
#define HALO 131                 // PW + 1
#define STRIP_PX (TILE_M + 2*HALO)   // 518
#define STRIP_B (STRIP_PX*128)       // 66304 bytes per half
#define TILES 67                 // ceil(PPX/TILE_M)
#define CPT 48                   // CTAs per task
#define JOBS (Bb*TILES)          // 536 per task

#define SW_OFF 0                 // weights: 9 taps x 2 halves x 8192 B = 147456
#define SA_OFF 147456            // A strip: 66304 B
#define BIAS_OFF (SA_OFF + STRIP_B)  // 213760
#define SMEM_TOT (BIAS_OFF + 256)    // 214016

// ---------------- device state ----------------
__device__ int g_sel[Tt*Ll];
// weights bf16: [mod 12][tap 9][half 2][oc 64][ic 64]
__device__ __align__(256) __nv_bfloat16 g_wB[(size_t)12*9*2*64*64];
// layer-0 input, padded NHWC bf16: [half][b][PTOT][64]
__device__ __align__(256) __nv_bfloat16 g_xp[2][(size_t)Bb*PTOT*Cc];
// ping-pong activations: [pp 2][half 2][t*b 24][PTOT][64]
__device__ __align__(256) __nv_bfloat16 g_act[2][2][(size_t)Tt*Bb*PTOT*Cc];

// ---------------- helpers ----------------
__device__ __forceinline__ uint32_t smem_u32(const void* p) {
    uint32_t a;
    asm("{ .reg .u64 t; cvta.to.shared.u64 t, %1; cvt.u32.u64 %0, t; }" : "=r"(a) : "l"(p));
    return a;
}
__device__ __forceinline__ void cp16(uint32_t sdst, const void* gsrc) {
    asm volatile("cp.async.cg.shared.global [%0], [%1], 16;" :: "r"(sdst), "l"(gsrc) : "memory");
}
__device__ __forceinline__ void cp_commit() { asm volatile("cp.async.commit_group;" ::: "memory"); }
__device__ __forceinline__ void cp_wait0() { asm volatile("cp.async.wait_group 0;" ::: "memory"); }

__device__ __forceinline__ void ldmx4(uint32_t* r, uint32_t addr) {
    asm volatile("ldmatrix.sync.aligned.m8n8.x4.shared.b16 {%0,%1,%2,%3}, [%4];"
                 : "=r"(r[0]), "=r"(r[1]), "=r"(r[2]), "=r"(r[3]) : "r"(addr));
}
__device__ __forceinline__ void mma16816(float* c, const uint32_t* a, const uint32_t* b) {
    asm volatile("mma.sync.aligned.m16n8k16.row.col.f32.bf16.bf16.f32 "
                 "{%0,%1,%2,%3}, {%4,%5,%6,%7}, {%8,%9}, {%0,%1,%2,%3};"
                 : "+f"(c[0]), "+f"(c[1]), "+f"(c[2]), "+f"(c[3])
                 : "r"(a[0]), "r"(a[1]), "r"(a[2]), "r"(a[3]), "r"(b[0]), "r"(b[1]));
}

// ---------------- routing ----------------
__global__ void routing_kernel(const float* __restrict__ alpha0,
                               const float* __restrict__ alphas,
                               const float* __restrict__ g0,
                               const float* __restrict__ gs) {
    int t = threadIdx.x;
    if (t >= Tt) return;
    int idx = 0;
    {
        float best = -1e30f; int bi = 0;
        #pragma unroll
        for (int m = 0; m < Mm; m++) {
            float v = alpha0[t*Mm + m] + g0[t*Mm + m];
            if (v > best) { best = v; bi = m; }
        }
        idx = bi; g_sel[t*Ll + 0] = bi;
    }
    for (int l = 1; l < Ll; l++) {
        const float* a = alphas + ((((size_t)(l-1)*Tt + t)*Mm + idx)*Mm);
        const float* g = gs     + ((((size_t)(l-1)*Tt + t)*Mm + idx)*Mm);
        float best = -1e30f; int bi = 0;
        #pragma unroll
        for (int m = 0; m < Mm; m++) {
            float v = a[m] + g[m];
            if (v > best) { best = v; bi = m; }
        }
        idx = bi; g_sel[t*Ll + l] = bi;
    }
}

// ---------------- zero borders of all padded buffers ----------------
__global__ void __launch_bounds__(256) zero_border() {
    int p = blockIdx.x * 256 + threadIdx.x;
    if (p >= PTOT) return;
    int pos = p - FRONT;
    if (pos >= 0 && pos < PPX) {
        int y = pos / PW, xx = pos - y * PW;
        if (y >= 1 && y <= Hh && xx >= 1 && xx <= Ww) return;  // interior, written later
    }
    int ib = blockIdx.y;   // 0..111
    __nv_bfloat16* base;
    if (ib < 16) base = g_xp[ib >> 3] + (size_t)(ib & 7) * PTOT * Cc;
    else {
        int k = ib - 16; int arr = k / 24; int img = k % 24;
        base = g_act[arr >> 1][arr & 1] + (size_t)img * PTOT * Cc;
    }
    uint4 z = make_uint4(0, 0, 0, 0);
    uint4* d = (uint4*)(base + (size_t)p * Cc);
    #pragma unroll
    for (int q = 0; q < 8; q++) d[q] = z;
}

// ---------------- weight prep: OIHW fp32 -> [mod][tap][half][oc][ic] bf16 --
__global__ void __launch_bounds__(256) wprep(const float* __restrict__ enc_w) {
    int i = blockIdx.x * 256 + threadIdx.x;        // 12*9*64*64 = 442368
    int ic  = i & 63;
    int oc  = (i >> 6) & 63;
    int tap = (i >> 12) % 9;
    int mod = i / 36864;
    float w = enc_w[(((size_t)(mod*Cc + oc))*Cc + ic)*9 + tap];
    __nv_bfloat16 hi = __float2bfloat16(w);
    __nv_bfloat16 lo = __float2bfloat16(w - __bfloat162float(hi));
    size_t base = (((size_t)mod*9 + tap)*2) * 4096 + oc*64 + ic;
    g_wB[base] = hi;
    g_wB[base + 4096] = lo;
}

// ---------------- input prep: NCHW fp32 -> padded NHWC bf16 hi/lo ----------
__global__ void __launch_bounds__(256) xprep(const float* __restrict__ x) {
    int idx = blockIdx.x * 256 + threadIdx.x;      // 8*16384
    int b = idx >> 14;
    int px = idx & (HWp - 1);
    int y = px >> 7, xx = px & 127;
    const float* xs = x + ((size_t)b * Cc << 14) + px;
    uint32_t h[32], l[32];
    #pragma unroll
    for (int ic = 0; ic < Cc; ic += 2) {
        float v0 = xs[(size_t)ic * HWp];
        float v1 = xs[(size_t)(ic + 1) * HWp];
        __nv_bfloat16 h0 = __float2bfloat16(v0);
        __nv_bfloat16 h1 = __float2bfloat16(v1);
        __nv_bfloat16 l0 = __float2bfloat16(v0 - __bfloat162float(h0));
        __nv_bfloat16 l1 = __float2bfloat16(v1 - __bfloat162float(h1));
        h[ic >> 1] = (uint32_t)__bfloat16_as_ushort(h1) << 16 | __bfloat16_as_ushort(h0);
        l[ic >> 1] = (uint32_t)__bfloat16_as_ushort(l1) << 16 | __bfloat16_as_ushort(l0);
    }
    int p = (y + 1) * PW + (xx + 1);
    size_t doff = ((size_t)b * PTOT + FRONT + p) * Cc;
    uint4* dh = (uint4*)(g_xp[0] + doff);
    uint4* dl = (uint4*)(g_xp[1] + doff);
    const uint4* hs = (const uint4*)h;
    const uint4* ls = (const uint4*)l;
    #pragma unroll
    for (int q = 0; q < 8; q++) { dh[q] = hs[q]; dl[q] = ls[q]; }
}

// ---------------- conv pass: 9 taps x 4 ksteps of m16n8k16 ----------------
// acc[4][4][4]: [m-tile][n-tile][d-reg]. dual=true: use both B halves.
__device__ __forceinline__ void conv_pass(float (*acc)[4][4], uint32_t sb,
                                          int lane, int wm, int wn, bool dual) {
    const int arow = (lane & 15);          // row within 16-row A frag
    const int akhalf = (lane >> 4) * 16;   // 0 or 16 bytes
    const int ocl = (lane & 7) + ((lane >> 4) << 3);
    const int bkhalf = ((lane >> 3) & 1) * 16;

    for (int tap = 0; tap < 9; tap++) {
        const int dy = tap / 3 - 1, dx = tap % 3 - 1;
        const int pxoff = HALO + dy * PW + dx;
        const uint32_t bbh = sb + SW_OFF + (tap * 2) * 8192;
        const uint32_t bbl = bbh + 8192;

        // per-mt pixel/base (k-independent)
        int abase[4], axor[4];
        #pragma unroll
        for (int mt = 0; mt < 4; mt++) {
            int px = wm * 64 + mt * 16 + arow + pxoff;
            abase[mt] = px * 128;
            axor[mt] = (px & 7) << 4;
        }
        int obase[2], oxor[2];
        #pragma unroll
        for (int pr = 0; pr < 2; pr++) {
            int oc = wn * 32 + pr * 16 + ocl;
            obase[pr] = oc * 128;
            oxor[pr] = (oc & 7) << 4;
        }

        #pragma unroll
        for (int k = 0; k < 4; k++) {
            uint32_t aF[4][4];
            #pragma unroll
            for (int mt = 0; mt < 4; mt++) {
                uint32_t addr = sb + SA_OFF + abase[mt]
                              + ((k * 32 + akhalf) ^ axor[mt]);
                ldmx4(aF[mt], addr);
            }
            uint32_t bh[4][2], bl[4][2];
            #pragma unroll
            for (int pr = 0; pr < 2; pr++) {
                uint32_t off = obase[pr] + ((k * 32 + bkhalf) ^ oxor[pr]);
                uint32_t r[4];
                ldmx4(r, bbh + off);
                bh[pr*2][0] = r[0]; bh[pr*2][1] = r[1];
                bh[pr*2+1][0] = r[2]; bh[pr*2+1][1] = r[3];
                if (dual) {
                    ldmx4(r, bbl + off);
                    bl[pr*2][0] = r[0]; bl[pr*2][1] = r[1];
                    bl[pr*2+1][0] = r[2]; bl[pr*2+1][1] = r[3];
                }
            }
            #pragma unroll
            for (int mt = 0; mt < 4; mt++)
                #pragma unroll
                for (int nt = 0; nt < 4; nt++) {
                    mma16816(acc[mt][nt], aF[mt], bh[nt]);
                    if (dual) mma16816(acc[mt][nt], aF[mt], bl[nt]);
                }
        }
    }
}

// ---------------- conv layer kernel ----------------------------------------
__global__ void __launch_bounds__(256) conv_hmma(int layer, int l0, int ps, int pd,
                                                 const float* __restrict__ enc_b) {
    extern __shared__ __align__(1024) char smem[];
    const uint32_t sb = smem_u32(smem);
    const int tid = threadIdx.x;
    const int lane = tid & 31, wid = tid >> 5;
    const int wm = wid >> 1, wn = wid & 1;

    const int t = blockIdx.x / CPT;
    const int cidx = blockIdx.x % CPT;
    const int mod = layer * Mm + g_sel[t*Ll + layer];

    // stage weights (144 KB) once, swizzled
    {
        const char* wsrc = (const char*)g_wB + (size_t)mod * 147456;
        for (int g = tid; g < 9216; g += 256) {
            int tile = g >> 9;
            int o = (g & 511) * 16;
            int sw = o ^ ((o >> 3) & 0x70);
            cp16(sb + SW_OFF + tile * 8192 + sw, wsrc + tile * 8192 + o);
        }
        cp_commit();
    }
    float* biasf = (float*)(smem + BIAS_OFF);
    if (tid < 64) biasf[tid] = enc_b[mod * 64 + tid];

    auto src_half = [&](int half, int b) -> const __nv_bfloat16* {
        if (l0) return g_xp[half] + ((size_t)b * PTOT + FRONT) * Cc;
        return g_act[ps][half] + ((size_t)(t*Bb + b) * PTOT + FRONT) * Cc;
    };
    auto stage = [&](const __nv_bfloat16* src, int tb) {
        const char* g = (const char*)(src + (size_t)(tb - HALO) * Cc);
        for (int i = tid; i < STRIP_B / 16; i += 256) {
            int o = i * 16;
            int sw = o ^ ((o >> 3) & 0x70);
            cp16(sb + SA_OFF + sw, g + o);
        }
    };

    bool first = true;
    for (int j = cidx; j < JOBS; j += CPT) {
        const int b = j / TILES;
        const int tile = j % TILES;
        const int tb = tile * TILE_M;
        const int img = t * Bb + b;
        __nv_bfloat16* dst_h = g_act[pd][0] + ((size_t)img * PTOT + FRONT) * Cc;
        __nv_bfloat16* dst_l = g_act[pd][1] + ((size_t)img * PTOT + FRONT) * Cc;

        if (first) { stage(src_half(0, b), tb); cp_commit(); first = false; }
        cp_wait0();
        __syncthreads();                 // Ah ready (+ weights on job 0)

        float acc[4][4][4];
        #pragma unroll
        for (int mt = 0; mt < 4; mt++)
            #pragma unroll
            for (int nt = 0; nt < 4; nt++)
                #pragma unroll
                for (int r = 0; r < 4; r++) acc[mt][nt][r] = 0.f;

        conv_pass(acc, sb, lane, wm, wn, true);     // Ah*Bh + Ah*Bl
        __syncthreads();                            // A reads done
        stage(src_half(1, b), tb);                  // Al
        cp_commit();
        cp_wait0();
        __syncthreads();
        conv_pass(acc, sb, lane, wm, wn, false);    // Al*Bh
        __syncthreads();                            // A reads done

        // prefetch next job's Ah during epilogue
        int jn = j + CPT;
        if (jn < JOBS) {
            stage(src_half(0, jn / TILES), (jn % TILES) * TILE_M);
            cp_commit();
        }

        // epilogue: bias + relu + split hi/lo, store interior pixels
        const int g = lane >> 2, c2 = (lane & 3) * 2;
        #pragma unroll
        for (int mt = 0; mt < 4; mt++) {
            #pragma unroll
            for (int r = 0; r < 2; r++) {
                int row = wm * 64 + mt * 16 + g + r * 8;
                int p = tb + row;
                if (p < PPX) {
                    int y = p / PW, xx = p - y * PW;
                    if (y >= 1 && y <= Hh && xx >= 1 && xx <= Ww) {
                        size_t base = (size_t)p * Cc;
                        #pragma unroll
                        for (int nt = 0; nt < 4; nt++) {
                            int oc = wn * 32 + nt * 8 + c2;
                            float f0 = fmaxf(acc[mt][nt][r*2+0] + biasf[oc],     0.f);
                            float f1 = fmaxf(acc[mt][nt][r*2+1] + biasf[oc + 1], 0.f);
                            __nv_bfloat16 h0 = __float2bfloat16(f0);
                            __nv_bfloat16 h1 = __float2bfloat16(f1);
                            __nv_bfloat16 l0 = __float2bfloat16(f0 - __bfloat162float(h0));
                            __nv_bfloat16 l1 = __float2bfloat16(f1 - __bfloat162float(h1));
                            uint32_t hw = (uint32_t)__bfloat16_as_ushort(h1) << 16 | __bfloat16_as_ushort(h0);
                            uint32_t lw = (uint32_t)__bfloat16_as_ushort(l1) << 16 | __bfloat16_as_ushort(l0);
                            *(uint32_t*)(dst_h + base + oc) = hw;
                            *(uint32_t*)(dst_l + base + oc) = lw;
                        }
                    }
                }
            }
        }
    }
}

// ---------------- decoder: 1x1 conv -> 3 ch (+normalize t==2) --------------
__global__ void __launch_bounds__(256) decoder_kernel(
    const float* __restrict__ dec_w, const float* __restrict__ dec_b,
    float* __restrict__ out) {
    int idx = blockIdx.x * 256 + threadIdx.x;
    int px = idx & (HWp - 1);
    int tb = idx >> 14;
    int b = tb & 7;
    int t = tb >> 3;
    int y = px >> 7, xx = px & 127;
    int p = (y + 1) * PW + (xx + 1);

    size_t soff = ((size_t)(t * Bb + b) * PTOT + FRONT + p) * Cc;
    const uint4* sh = (const uint4*)(g_act[1][0] + soff);
    const uint4* sl = (const uint4*)(g_act[1][1] + soff);
    const float* w = dec_w + (size_t)t * 3 * Cc;

    float a0 = dec_b[t*3 + 0];
    float a1 = dec_b[t*3 + 1];
    float a2 = dec_b[t*3 + 2];
    #pragma unroll
    for (int q = 0; q < 8; q++) {
        uint4 vh = sh[q], vl = sl[q];
        uint32_t hws[4] = {vh.x, vh.y, vh.z, vh.w};
        uint32_t lws[4] = {vl.x, vl.y, vl.z, vl.w};
        #pragma unroll
        for (int j = 0; j < 4; j++) {
            #pragma unroll
            for (int e = 0; e < 2; e++) {
                int ic = q*8 + j*2 + e;
                float hv = __bfloat162float(__ushort_as_bfloat16((hws[j] >> (16*e)) & 0xFFFF));
                float lv = __bfloat162float(__ushort_as_bfloat16((lws[j] >> (16*e)) & 0xFFFF));
                float v = hv + lv;
                a0 = fmaf(v, __ldg(w + ic), a0);
                a1 = fmaf(v, __ldg(w + Cc + ic), a1);
                a2 = fmaf(v, __ldg(w + 2*Cc + ic), a2);
            }
        }
    }
    if (t == 2) {
        float n = rsqrtf(a0*a0 + a1*a1 + a2*a2);
        a0 *= n; a1 *= n; a2 *= n;
    }
    float* op = out + ((size_t)(t * Bb + b) * 3) * HWp + px;
    op[0] = a0;
    op[HWp] = a1;
    op[2*HWp] = a2;
}

extern "C" void kernel_launch(void* const* d_in, const int* in_sizes, int n_in,
                              void* d_out, int out_size) {
    const float* x      = (const float*)d_in[0];
    const float* alpha0 = (const float*)d_in[1];
    const float* alphas = (const float*)d_in[2];
    const float* g0     = (const float*)d_in[3];
    const float* gs     = (const float*)d_in[4];
    const float* enc_w  = (const float*)d_in[5];
    const float* enc_b  = (const float*)d_in[6];
    const float* dec_w  = (const float*)d_in[7];
    const float* dec_b  = (const float*)d_in[8];
    float* out = (float*)d_out;

    cudaFuncSetAttribute(conv_hmma, cudaFuncAttributeMaxDynamicSharedMemorySize, SMEM_TOT);

    zero_border<<<dim3((PTOT + 255) / 256, 112), 256>>>();
    routing_kernel<<<1, 32>>>(alpha0, alphas, g0, gs);
    wprep<<<1728, 256>>>(enc_w);
    xprep<<<(Bb * HWp) / 256, 256>>>(x);

    conv_hmma<<<Tt*CPT, 256, SMEM_TOT>>>(0, 1, 0, 0, enc_b);
    conv_hmma<<<Tt*CPT, 256, SMEM_TOT>>>(1, 0, 0, 1, enc_b);
    conv_hmma<<<Tt*CPT, 256, SMEM_TOT>>>(2, 0, 1, 0, enc_b);
    conv_hmma<<<Tt*CPT, 256, SMEM_TOT>>>(3, 0, 0, 1, enc_b);

    decoder_kernel<<<(Tt*Bb*HWp) / 256, 256>>>(dec_w, dec_b, out);
}

// round 5
// speedup vs baseline: 8.9487x; 1.1067x over previous
#include <cuda_runtime.h>
#include <cuda_bf16.h>
#include <cstdint>

#define Tt 3
#define Ll 4
#define Mm 3
#define Bb 8
#define Cc 64
#define Hh 128
#define Ww 128
#define HWp (Hh*Ww)
#define PW 130
#define PPX (PW*PW)              // 16900 padded pixels
#define FRONT 256
#define SLACK 384
#define PTOT (FRONT + PPX + SLACK)

#define TILE_M 256
#define HALO 131                 // PW + 1
#define STRIP_PX (TILE_M + 2*HALO)   // 518
#define STRIP_B (STRIP_PX*128)       // 66304 bytes per half
#define TILES 67                 // ceil(PPX/TILE_M)
#define CTAS 148
#define JOBS (Tt*Bb*TILES)       // 1608 jobs per layer

#define SW_OFF 0                 // weights: 9 taps x 2 halves x 8192 B = 147456
#define SA_OFF 147456            // A strip: 66304 B
#define DBUF_OFF (SA_OFF + STRIP_B)  // decoder reduce buf: 256*2*3*4 = 6144
#define SMEM_TOT (DBUF_OFF + 6144)   // 219904

// ---------------- device state ----------------
__device__ int g_sel[Tt*Ll];
// weights bf16: [mod 12][tap 9][half 2][oc 64][ic 64]
__device__ __align__(256) __nv_bfloat16 g_wB[(size_t)12*9*2*64*64];
// layer-0 input, padded NHWC bf16: [half][b][PTOT][64]
__device__ __align__(256) __nv_bfloat16 g_xp[2][(size_t)Bb*PTOT*Cc];
// ping-pong activations: [pp 2][half 2][t*b 24][PTOT][64]
__device__ __align__(256) __nv_bfloat16 g_act[2][2][(size_t)Tt*Bb*PTOT*Cc];

// ---------------- helpers ----------------
__device__ __forceinline__ uint32_t smem_u32(const void* p) {
    uint32_t a;
    asm("{ .reg .u64 t; cvta.to.shared.u64 t, %1; cvt.u32.u64 %0, t; }" : "=r"(a) : "l"(p));
    return a;
}
__device__ __forceinline__ void cp16(uint32_t sdst, const void* gsrc) {
    asm volatile("cp.async.cg.shared.global [%0], [%1], 16;" :: "r"(sdst), "l"(gsrc) : "memory");
}
__device__ __forceinline__ void cp_commit() { asm volatile("cp.async.commit_group;" ::: "memory"); }
__device__ __forceinline__ void cp_wait0() { asm volatile("cp.async.wait_group 0;" ::: "memory"); }

__device__ __forceinline__ void ldmx4(uint32_t* r, uint32_t addr) {
    asm volatile("ldmatrix.sync.aligned.m8n8.x4.shared.b16 {%0,%1,%2,%3}, [%4];"
                 : "=r"(r[0]), "=r"(r[1]), "=r"(r[2]), "=r"(r[3]) : "r"(addr));
}
__device__ __forceinline__ void mma16816(float* c, const uint32_t* a, const uint32_t* b) {
    asm volatile("mma.sync.aligned.m16n8k16.row.col.f32.bf16.bf16.f32 "
                 "{%0,%1,%2,%3}, {%4,%5,%6,%7}, {%8,%9}, {%0,%1,%2,%3};"
                 : "+f"(c[0]), "+f"(c[1]), "+f"(c[2]), "+f"(c[3])
                 : "r"(a[0]), "r"(a[1]), "r"(a[2]), "r"(a[3]), "r"(b[0]), "r"(b[1]));
}

// ---------------- routing ----------------
__global__ void routing_kernel(const float* __restrict__ alpha0,
                               const float* __restrict__ alphas,
                               const float* __restrict__ g0,
                               const float* __restrict__ gs) {
    int t = threadIdx.x;
    if (t >= Tt) return;
    int idx = 0;
    {
        float best = -1e30f; int bi = 0;
        #pragma unroll
        for (int m = 0; m < Mm; m++) {
            float v = alpha0[t*Mm + m] + g0[t*Mm + m];
            if (v > best) { best = v; bi = m; }
        }
        idx = bi; g_sel[t*Ll + 0] = bi;
    }
    for (int l = 1; l < Ll; l++) {
        const float* a = alphas + ((((size_t)(l-1)*Tt + t)*Mm + idx)*Mm);
        const float* g = gs     + ((((size_t)(l-1)*Tt + t)*Mm + idx)*Mm);
        float best = -1e30f; int bi = 0;
        #pragma unroll
        for (int m = 0; m < Mm; m++) {
            float v = a[m] + g[m];
            if (v > best) { best = v; bi = m; }
        }
        idx = bi; g_sel[t*Ll + l] = bi;
    }
}

// ---------------- zero borders of all padded buffers ----------------
__global__ void __launch_bounds__(256) zero_border() {
    int p = blockIdx.x * 256 + threadIdx.x;
    if (p >= PTOT) return;
    int pos = p - FRONT;
    if (pos >= 0 && pos < PPX) {
        int y = pos / PW, xx = pos - y * PW;
        if (y >= 1 && y <= Hh && xx >= 1 && xx <= Ww) return;  // interior, written later
    }
    int ib = blockIdx.y;   // 0..111
    __nv_bfloat16* base;
    if (ib < 16) base = g_xp[ib >> 3] + (size_t)(ib & 7) * PTOT * Cc;
    else {
        int k = ib - 16; int arr = k / 24; int img = k % 24;
        base = g_act[arr >> 1][arr & 1] + (size_t)img * PTOT * Cc;
    }
    uint4 z = make_uint4(0, 0, 0, 0);
    uint4* d = (uint4*)(base + (size_t)p * Cc);
    #pragma unroll
    for (int q = 0; q < 8; q++) d[q] = z;
}

// ---------------- weight prep: OIHW fp32 -> [mod][tap][half][oc][ic] bf16 --
__global__ void __launch_bounds__(256) wprep(const float* __restrict__ enc_w) {
    int i = blockIdx.x * 256 + threadIdx.x;        // 12*9*64*64 = 442368
    int ic  = i & 63;
    int oc  = (i >> 6) & 63;
    int tap = (i >> 12) % 9;
    int mod = i / 36864;
    float w = enc_w[(((size_t)(mod*Cc + oc))*Cc + ic)*9 + tap];
    __nv_bfloat16 hi = __float2bfloat16(w);
    __nv_bfloat16 lo = __float2bfloat16(w - __bfloat162float(hi));
    size_t base = (((size_t)mod*9 + tap)*2) * 4096 + oc*64 + ic;
    g_wB[base] = hi;
    g_wB[base + 4096] = lo;
}

// ---------------- input prep: NCHW fp32 -> padded NHWC bf16 hi/lo ----------
__global__ void __launch_bounds__(256) xprep(const float* __restrict__ x) {
    int idx = blockIdx.x * 256 + threadIdx.x;      // 8*16384
    int b = idx >> 14;
    int px = idx & (HWp - 1);
    int y = px >> 7, xx = px & 127;
    const float* xs = x + ((size_t)b * Cc << 14) + px;
    uint32_t h[32], l[32];
    #pragma unroll
    for (int ic = 0; ic < Cc; ic += 2) {
        float v0 = xs[(size_t)ic * HWp];
        float v1 = xs[(size_t)(ic + 1) * HWp];
        __nv_bfloat16 h0 = __float2bfloat16(v0);
        __nv_bfloat16 h1 = __float2bfloat16(v1);
        __nv_bfloat16 l0 = __float2bfloat16(v0 - __bfloat162float(h0));
        __nv_bfloat16 l1 = __float2bfloat16(v1 - __bfloat162float(h1));
        h[ic >> 1] = (uint32_t)__bfloat16_as_ushort(h1) << 16 | __bfloat16_as_ushort(h0);
        l[ic >> 1] = (uint32_t)__bfloat16_as_ushort(l1) << 16 | __bfloat16_as_ushort(l0);
    }
    int p = (y + 1) * PW + (xx + 1);
    size_t doff = ((size_t)b * PTOT + FRONT + p) * Cc;
    uint4* dh = (uint4*)(g_xp[0] + doff);
    uint4* dl = (uint4*)(g_xp[1] + doff);
    const uint4* hs = (const uint4*)h;
    const uint4* ls = (const uint4*)l;
    #pragma unroll
    for (int q = 0; q < 8; q++) { dh[q] = hs[q]; dl[q] = ls[q]; }
}

// ---------------- conv pass: 9 taps x 4 ksteps of m16n8k16 ----------------
__device__ __forceinline__ void conv_pass(float (*acc)[4][4], uint32_t sb,
                                          int lane, int wm, int wn, bool dual) {
    const int arow = (lane & 15);
    const int akhalf = (lane >> 4) * 16;
    const int ocl = (lane & 7) + ((lane >> 4) << 3);
    const int bkhalf = ((lane >> 3) & 1) * 16;

    for (int tap = 0; tap < 9; tap++) {
        const int dy = tap / 3 - 1, dx = tap % 3 - 1;
        const int pxoff = HALO + dy * PW + dx;
        const uint32_t bbh = sb + SW_OFF + (tap * 2) * 8192;
        const uint32_t bbl = bbh + 8192;

        int abase[4], axor[4];
        #pragma unroll
        for (int mt = 0; mt < 4; mt++) {
            int px = wm * 64 + mt * 16 + arow + pxoff;
            abase[mt] = px * 128;
            axor[mt] = (px & 7) << 4;
        }
        int obase[2], oxor[2];
        #pragma unroll
        for (int pr = 0; pr < 2; pr++) {
            int oc = wn * 32 + pr * 16 + ocl;
            obase[pr] = oc * 128;
            oxor[pr] = (oc & 7) << 4;
        }

        #pragma unroll
        for (int k = 0; k < 4; k++) {
            uint32_t aF[4][4];
            #pragma unroll
            for (int mt = 0; mt < 4; mt++) {
                uint32_t addr = sb + SA_OFF + abase[mt]
                              + ((k * 32 + akhalf) ^ axor[mt]);
                ldmx4(aF[mt], addr);
            }
            uint32_t bh[4][2], bl[4][2];
            #pragma unroll
            for (int pr = 0; pr < 2; pr++) {
                uint32_t off = obase[pr] + ((k * 32 + bkhalf) ^ oxor[pr]);
                uint32_t r[4];
                ldmx4(r, bbh + off);
                bh[pr*2][0] = r[0]; bh[pr*2][1] = r[1];
                bh[pr*2+1][0] = r[2]; bh[pr*2+1][1] = r[3];
                if (dual) {
                    ldmx4(r, bbl + off);
                    bl[pr*2][0] = r[0]; bl[pr*2][1] = r[1];
                    bl[pr*2+1][0] = r[2]; bl[pr*2+1][1] = r[3];
                }
            }
            #pragma unroll
            for (int mt = 0; mt < 4; mt++)
                #pragma unroll
                for (int nt = 0; nt < 4; nt++) {
                    mma16816(acc[mt][nt], aF[mt], bh[nt]);
                    if (dual) mma16816(acc[mt][nt], aF[mt], bl[nt]);
                }
        }
    }
}

// ---------------- conv layer kernel (unified job grid) ----------------------
__global__ void __launch_bounds__(256) conv_hmma(
    int layer, int l0, int ps, int pd,
    const float* __restrict__ enc_b,
    const float* __restrict__ dec_w, const float* __restrict__ dec_b,
    float* __restrict__ out)
{
    extern __shared__ __align__(1024) char smem[];
    const uint32_t sb = smem_u32(smem);
    float (*dbuf)[2][3] = (float (*)[2][3])(smem + DBUF_OFF);
    const int tid = threadIdx.x;
    const int lane = tid & 31, wid = tid >> 5;
    const int wm = wid >> 1, wn = wid & 1;
    const int cta = blockIdx.x;

    // contiguous job partition: JOBS=1608 over 148 CTAs (q=10, r=128)
    const int nj = (cta < 128) ? 11 : 10;
    int j = (cta < 128) ? cta * 11 : 128 * 11 + (cta - 128) * 10;

    auto src_half = [&](int half, int img) -> const __nv_bfloat16* {
        if (l0) return g_xp[half] + ((size_t)(img & 7) * PTOT + FRONT) * Cc;
        return g_act[ps][half] + ((size_t)img * PTOT + FRONT) * Cc;
    };
    auto stage = [&](const __nv_bfloat16* src, int tb) {
        const char* g = (const char*)(src + (size_t)(tb - HALO) * Cc);
        for (int i = tid; i < STRIP_B / 16; i += 256) {
            int o = i * 16;
            int sw = o ^ ((o >> 3) & 0x70);
            cp16(sb + SA_OFF + sw, g + o);
        }
    };
    auto stage_w = [&](int mod) {
        const char* wsrc = (const char*)g_wB + (size_t)mod * 147456;
        for (int g = tid; g < 9216; g += 256) {
            int tile = g >> 9;
            int o = (g & 511) * 16;
            int sw = o ^ ((o >> 3) & 0x70);
            cp16(sb + SW_OFF + tile * 8192 + sw, wsrc + tile * 8192 + o);
        }
    };

    int cur_mod = -1;

    for (int jj = 0; jj < nj; jj++, j++) {
        const int img = j / TILES;
        const int tile = j - img * TILES;
        const int t = img >> 3;
        const int tb = tile * TILE_M;
        const int mod = layer * Mm + g_sel[t*Ll + layer];

        if (jj == 0) {
            stage_w(mod);
            stage(src_half(0, img), tb);
            cur_mod = mod;
            cp_commit();
        } else if (mod != cur_mod) {
            stage_w(mod);          // prev tile fully synced; Ah prefetch already issued
            cur_mod = mod;
            cp_commit();
        }
        cp_wait0();
        __syncthreads();           // Ah (+weights) ready

        float acc[4][4][4];
        #pragma unroll
        for (int mt = 0; mt < 4; mt++)
            #pragma unroll
            for (int nt = 0; nt < 4; nt++)
                #pragma unroll
                for (int r = 0; r < 4; r++) acc[mt][nt][r] = 0.f;

        conv_pass(acc, sb, lane, wm, wn, true);     // Ah*Bh + Ah*Bl
        __syncthreads();
        stage(src_half(1, img), tb);                // Al
        cp_commit();
        cp_wait0();
        __syncthreads();
        conv_pass(acc, sb, lane, wm, wn, false);    // Al*Bh
        __syncthreads();                            // A reads done

        // prefetch next job's Ah during epilogue
        if (jj + 1 < nj) {
            int j2 = j + 1;
            int img2 = j2 / TILES;
            int tile2 = j2 - img2 * TILES;
            stage(src_half(0, img2), tile2 * TILE_M);
            cp_commit();
        }

        const int g = lane >> 2, c2 = (lane & 3) * 2;
        const float* bb = enc_b + mod * 64;

        if (layer != 3) {
            // epilogue: bias + relu + split hi/lo, store interior pixels
            __nv_bfloat16* dst_h = g_act[pd][0] + ((size_t)img * PTOT + FRONT) * Cc;
            __nv_bfloat16* dst_l = g_act[pd][1] + ((size_t)img * PTOT + FRONT) * Cc;
            #pragma unroll
            for (int mt = 0; mt < 4; mt++) {
                #pragma unroll
                for (int r = 0; r < 2; r++) {
                    int row = wm * 64 + mt * 16 + g + r * 8;
                    int p = tb + row;
                    if (p < PPX) {
                        int y = p / PW, xx = p - y * PW;
                        if (y >= 1 && y <= Hh && xx >= 1 && xx <= Ww) {
                            size_t base = (size_t)p * Cc;
                            #pragma unroll
                            for (int nt = 0; nt < 4; nt++) {
                                int oc = wn * 32 + nt * 8 + c2;
                                float f0 = fmaxf(acc[mt][nt][r*2+0] + __ldg(bb + oc),     0.f);
                                float f1 = fmaxf(acc[mt][nt][r*2+1] + __ldg(bb + oc + 1), 0.f);
                                __nv_bfloat16 h0 = __float2bfloat16(f0);
                                __nv_bfloat16 h1 = __float2bfloat16(f1);
                                __nv_bfloat16 l0 = __float2bfloat16(f0 - __bfloat162float(h0));
                                __nv_bfloat16 l1 = __float2bfloat16(f1 - __bfloat162float(h1));
                                uint32_t hw = (uint32_t)__bfloat16_as_ushort(h1) << 16 | __bfloat16_as_ushort(h0);
                                uint32_t lw = (uint32_t)__bfloat16_as_ushort(l1) << 16 | __bfloat16_as_ushort(l0);
                                *(uint32_t*)(dst_h + base + oc) = hw;
                                *(uint32_t*)(dst_l + base + oc) = lw;
                            }
                        }
                    }
                }
            }
        } else {
            // fused decoder: per-thread partial dot with dec_w over its 8 ocs
            float wd[3][8];
            #pragma unroll
            for (int kk = 0; kk < 3; kk++)
                #pragma unroll
                for (int q = 0; q < 8; q++) {
                    int oc = wn * 32 + (q >> 1) * 8 + c2 + (q & 1);
                    wd[kk][q] = __ldg(dec_w + ((size_t)t * 3 + kk) * 64 + oc);
                }
            #pragma unroll
            for (int mt = 0; mt < 4; mt++) {
                #pragma unroll
                for (int r = 0; r < 2; r++) {
                    float p0 = 0.f, p1 = 0.f, p2 = 0.f;
                    #pragma unroll
                    for (int nt = 0; nt < 4; nt++) {
                        int oc = wn * 32 + nt * 8 + c2;
                        float f0 = fmaxf(acc[mt][nt][r*2+0] + __ldg(bb + oc),     0.f);
                        float f1 = fmaxf(acc[mt][nt][r*2+1] + __ldg(bb + oc + 1), 0.f);
                        p0 = fmaf(f0, wd[0][nt*2+0], fmaf(f1, wd[0][nt*2+1], p0));
                        p1 = fmaf(f0, wd[1][nt*2+0], fmaf(f1, wd[1][nt*2+1], p1));
                        p2 = fmaf(f0, wd[2][nt*2+0], fmaf(f1, wd[2][nt*2+1], p2));
                    }
                    #pragma unroll
                    for (int off = 1; off < 4; off <<= 1) {
                        p0 += __shfl_xor_sync(0xffffffffu, p0, off);
                        p1 += __shfl_xor_sync(0xffffffffu, p1, off);
                        p2 += __shfl_xor_sync(0xffffffffu, p2, off);
                    }
                    if ((lane & 3) == 0) {
                        int pix = wm * 64 + mt * 16 + r * 8 + g;
                        dbuf[pix][wn][0] = p0;
                        dbuf[pix][wn][1] = p1;
                        dbuf[pix][wn][2] = p2;
                    }
                }
            }
            __syncthreads();
            {
                int p = tb + tid;
                if (p < PPX) {
                    int y = p / PW, xx = p - y * PW;
                    if (y >= 1 && y <= Hh && xx >= 1 && xx <= Ww) {
                        float a0 = dbuf[tid][0][0] + dbuf[tid][1][0] + __ldg(dec_b + t*3 + 0);
                        float a1 = dbuf[tid][0][1] + dbuf[tid][1][1] + __ldg(dec_b + t*3 + 1);
                        float a2 = dbuf[tid][0][2] + dbuf[tid][1][2] + __ldg(dec_b + t*3 + 2);
                        if (t == 2) {
                            float n = rsqrtf(a0*a0 + a1*a1 + a2*a2);
                            a0 *= n; a1 *= n; a2 *= n;
                        }
                        float* op = out + ((size_t)img * 3) * HWp + (y - 1) * Ww + (xx - 1);
                        op[0] = a0;
                        op[HWp] = a1;
                        op[2*HWp] = a2;
                    }
                }
            }
        }
    }
}

extern "C" void kernel_launch(void* const* d_in, const int* in_sizes, int n_in,
                              void* d_out, int out_size) {
    const float* x      = (const float*)d_in[0];
    const float* alpha0 = (const float*)d_in[1];
    const float* alphas = (const float*)d_in[2];
    const float* g0     = (const float*)d_in[3];
    const float* gs     = (const float*)d_in[4];
    const float* enc_w  = (const float*)d_in[5];
    const float* enc_b  = (const float*)d_in[6];
    const float* dec_w  = (const float*)d_in[7];
    const float* dec_b  = (const float*)d_in[8];
    float* out = (float*)d_out;

    cudaFuncSetAttribute(conv_hmma, cudaFuncAttributeMaxDynamicSharedMemorySize, SMEM_TOT);

    zero_border<<<dim3((PTOT + 255) / 256, 112), 256>>>();
    routing_kernel<<<1, 32>>>(alpha0, alphas, g0, gs);
    wprep<<<1728, 256>>>(enc_w);
    xprep<<<(Bb * HWp) / 256, 256>>>(x);

    conv_hmma<<<CTAS, 256, SMEM_TOT>>>(0, 1, 0, 0, enc_b, dec_w, dec_b, out);
    conv_hmma<<<CTAS, 256, SMEM_TOT>>>(1, 0, 0, 1, enc_b, dec_w, dec_b, out);
    conv_hmma<<<CTAS, 256, SMEM_TOT>>>(2, 0, 1, 0, enc_b, dec_w, dec_b, out);
    conv_hmma<<<CTAS, 256, SMEM_TOT>>>(3, 0, 0, 1, enc_b, dec_w, dec_b, out);
}